// round 5
// baseline (speedup 1.0000x reference)
#include <cuda_runtime.h>
#include <cuda_bf16.h>
#include <math.h>
#include <stdint.h>

#define BSZ 8
#define LSEQ 4096
#define DM 512
#define NS 64
#define NROWS (BSZ*LSEQ)

// scratch (allocations forbidden -> device globals)
__device__ __align__(16) float g_states[NROWS*NS];
__device__ __align__(16) __nv_bfloat16 g_Bhi[NS*DM];
__device__ __align__(16) __nv_bfloat16 g_Blo[NS*DM];
__device__ __align__(16) __nv_bfloat16 g_Chi[DM*NS];
__device__ __align__(16) __nv_bfloat16 g_Clo[DM*NS];
__device__ __align__(16) __nv_bfloat16 g_Mhi[3*NS*NS];
__device__ __align__(16) __nv_bfloat16 g_Mlo[3*NS*NS];

// ===================== helpers (sm_80-era PTX only) =====================
__device__ __forceinline__ uint32_t smem_u32(const void* p) {
    uint32_t a;
    asm("{ .reg .u64 t; cvta.to.shared.u64 t, %1; cvt.u32.u64 %0, t; }" : "=r"(a) : "l"(p));
    return a;
}
#define SW(o) ((uint32_t)(o) ^ ((((uint32_t)(o)) >> 3) & 0x70))

__device__ __forceinline__ void ldsm4(uint32_t r[4], uint32_t addr) {
    asm volatile("ldmatrix.sync.aligned.m8n8.x4.shared.b16 {%0,%1,%2,%3}, [%4];"
        : "=r"(r[0]), "=r"(r[1]), "=r"(r[2]), "=r"(r[3]) : "r"(addr));
}
__device__ __forceinline__ void mma_bf16(float c[4], const uint32_t a[4],
                                         uint32_t b0, uint32_t b1) {
    asm volatile("mma.sync.aligned.m16n8k16.row.col.f32.bf16.bf16.f32 "
        "{%0,%1,%2,%3}, {%4,%5,%6,%7}, {%8,%9}, {%0,%1,%2,%3};"
        : "+f"(c[0]), "+f"(c[1]), "+f"(c[2]), "+f"(c[3])
        : "r"(a[0]), "r"(a[1]), "r"(a[2]), "r"(a[3]), "r"(b0), "r"(b1));
}
__device__ __forceinline__ void split_pair(float a, float b, uint32_t& h, uint32_t& l) {
    __nv_bfloat16 ha = __float2bfloat16_rn(a), hb = __float2bfloat16_rn(b);
    float ra = a - __bfloat162float(ha);
    float rb = b - __bfloat162float(hb);
    __nv_bfloat16 la = __float2bfloat16_rn(ra), lb = __float2bfloat16_rn(rb);
    h = (uint32_t)__bfloat16_as_ushort(ha) | ((uint32_t)__bfloat16_as_ushort(hb) << 16);
    l = (uint32_t)__bfloat16_as_ushort(la) | ((uint32_t)__bfloat16_as_ushort(lb) << 16);
}
__device__ __forceinline__ float gelu_exact(float v) {
    return 0.5f * v * (1.0f + erff(v * 0.70710678118654752440f));
}

// ---------------------------------------------------------------------------
// prep: A2=A@A, A4=A2@A2, write bf16 hi/lo splits of A,A2,A4
// ---------------------------------------------------------------------------
__global__ void prep_kernel(const float* __restrict__ A) {
    __shared__ float As[NS*NS], A2s[NS*NS], A4s[NS*NS];
    int tid = threadIdx.x;
    for (int i = tid; i < NS*NS; i += 256) As[i] = A[i];
    __syncthreads();
    for (int e = tid; e < NS*NS; e += 256) {
        int n = e >> 6, m = e & 63;
        float acc = 0.f;
        #pragma unroll 8
        for (int k = 0; k < NS; k++) acc += As[n*NS + k] * As[k*NS + m];
        A2s[e] = acc;
    }
    __syncthreads();
    for (int e = tid; e < NS*NS; e += 256) {
        int n = e >> 6, m = e & 63;
        float acc = 0.f;
        #pragma unroll 8
        for (int k = 0; k < NS; k++) acc += A2s[n*NS + k] * A2s[k*NS + m];
        A4s[e] = acc;
    }
    __syncthreads();
    for (int e = tid; e < NS*NS; e += 256) {
        float vs[3] = {As[e], A2s[e], A4s[e]};
        #pragma unroll
        for (int p = 0; p < 3; p++) {
            __nv_bfloat16 h = __float2bfloat16_rn(vs[p]);
            g_Mhi[p*NS*NS + e] = h;
            g_Mlo[p*NS*NS + e] = __float2bfloat16_rn(vs[p] - __bfloat162float(h));
        }
    }
}

// ---------------------------------------------------------------------------
// split B [64,512] and C [512,64] into bf16 hi/lo globals
// ---------------------------------------------------------------------------
__global__ void split_wb(const float* __restrict__ B, const float* __restrict__ C) {
    int stride = gridDim.x * blockDim.x;
    for (int i = blockIdx.x*blockDim.x + threadIdx.x; i < 16384; i += stride) {
        float4 v = (i < 8192) ? ((const float4*)B)[i] : ((const float4*)C)[i - 8192];
        uint32_t h0, l0, h1, l1;
        split_pair(v.x, v.y, h0, l0);
        split_pair(v.z, v.w, h1, l1);
        uint2 hh = make_uint2(h0, h1), ll = make_uint2(l0, l1);
        if (i < 8192) { ((uint2*)g_Bhi)[i] = hh;        ((uint2*)g_Blo)[i] = ll; }
        else          { ((uint2*)g_Chi)[i - 8192] = hh; ((uint2*)g_Clo)[i - 8192] = ll; }
    }
}

// ---------------------------------------------------------------------------
// Fused stages 1+2: Bu = x@B^T (136 rows incl. 8-row halo, N=64, K=512) via
// HMMA, accumulators stay in registers as the identity term, then three
// chained shift-GEMM passes (out = in + A^{1,2,4} * shift(in)) in-block.
// smem row r <-> t = t0 - 16 + r; rows 0..7 and 144..151 zero pads.
// ---------------------------------------------------------------------------
#define F_AHI 0
#define F_ALO 19456
#define F_R2  38912
#define F_BHI F_R2
#define F_BLO (F_R2 + 8192)
#define F_MHI F_R2
#define F_MLO (F_R2 + 24576)
#define F_SMEM (F_R2 + 49152)

__global__ __launch_bounds__(288) void bupass_mma(const float* __restrict__ x) {
    extern __shared__ char sm[];
    uint32_t smb = smem_u32(sm);
    int tid = threadIdx.x, wid = tid >> 5, lane = tid & 31;
    int b = blockIdx.x >> 5, c = blockIdx.x & 31;
    int t0 = c * 128;
    size_t gbase = (size_t)b * LSEQ;

    int i0 = 8 + wid*16;
    int rg = lane >> 2, q = lane & 3;
    int a_r = lane & 15, a_k = (lane >> 4) << 4;
    int b_m = lane >> 3;
    int b_n = ((b_m >> 1) << 3) + (lane & 7);
    int b_k = (b_m & 1) << 4;

    float acc[8][4];
    #pragma unroll
    for (int nf = 0; nf < 8; nf++)
        #pragma unroll
        for (int cc = 0; cc < 4; cc++) acc[nf][cc] = 0.f;

    // ---- stage A: Bu via HMMA over 8 K-chunks of 64 ----
    for (int kc = 0; kc < 8; kc++) {
        if (kc) __syncthreads();
        // stage x chunk rows 0..151 (zero pads / t<0 guard), bf16 hi/lo SW128
        for (int f = tid; f < 152*16; f += 288) {
            int r = f >> 4, c4 = (f & 15) << 2;
            int t = t0 - 16 + r;
            float4 v = make_float4(0.f, 0.f, 0.f, 0.f);
            if (r >= 8 && r < 144 && t >= 0)
                v = *(const float4*)&x[(gbase + t)*DM + kc*64 + c4];
            uint32_t h0, l0, h1, l1;
            split_pair(v.x, v.y, h0, l0);
            split_pair(v.z, v.w, h1, l1);
            uint32_t off = SW(r*128 + c4*2);
            *(uint2*)(sm + F_AHI + off) = make_uint2(h0, h1);
            *(uint2*)(sm + F_ALO + off) = make_uint2(l0, l1);
        }
        // stage B chunk [64 n][64 k] hi/lo (pre-split)
        for (int f = tid; f < 1024; f += 288) {
            int buf = f >> 9, rem = f & 511, n = rem >> 3, j = rem & 7;
            uint4 v = ((const uint4*)(buf ? g_Blo : g_Bhi))[n*64 + kc*8 + j];
            *(uint4*)(sm + (buf ? F_BLO : F_BHI) + SW(n*128 + j*16)) = v;
        }
        __syncthreads();
        #pragma unroll
        for (int ks = 0; ks < 4; ks++) {
            uint32_t ah[4], al[4];
            uint32_t aoff = SW((i0 + a_r)*128 + ks*32 + a_k);
            ldsm4(ah, smb + F_AHI + aoff);
            ldsm4(al, smb + F_ALO + aoff);
            #pragma unroll
            for (int nfp = 0; nfp < 4; nfp++) {
                uint32_t boff = SW((nfp*16 + b_n)*128 + ks*32 + b_k);
                uint32_t bh[4], bl[4];
                ldsm4(bh, smb + F_BHI + boff);
                ldsm4(bl, smb + F_BLO + boff);
                mma_bf16(acc[2*nfp],   ah, bh[0], bh[1]);
                mma_bf16(acc[2*nfp],   ah, bl[0], bl[1]);
                mma_bf16(acc[2*nfp],   al, bh[0], bh[1]);
                mma_bf16(acc[2*nfp+1], ah, bh[2], bh[3]);
                mma_bf16(acc[2*nfp+1], ah, bl[2], bl[3]);
                mma_bf16(acc[2*nfp+1], al, bh[2], bh[3]);
            }
        }
    }
    __syncthreads();   // all stage-A reads done; buffers free for reuse

    // spill split(Bu) into the A-operand buffer (rows 0..7 stay zero from
    // the last staging pass; warp 8 writes zeros to rows 144..151)
    int r0 = i0 + rg, r1 = r0 + 8;
    #pragma unroll
    for (int nf = 0; nf < 8; nf++) {
        int colb = (nf*8 + q*2)*2;
        uint32_t h, l;
        split_pair(acc[nf][0], acc[nf][1], h, l);
        uint32_t off = SW(r0*128 + colb);
        *(uint32_t*)(sm + F_AHI + off) = h;
        *(uint32_t*)(sm + F_ALO + off) = l;
        split_pair(acc[nf][2], acc[nf][3], h, l);
        off = SW(r1*128 + colb);
        *(uint32_t*)(sm + F_AHI + off) = h;
        *(uint32_t*)(sm + F_ALO + off) = l;
    }
    // stage A,A2,A4 splits (overwrites B-chunk region; reads finished)
    for (int f = tid; f < 3072; f += 288) {
        int p = f >> 10, rem = f & 1023, buf = rem >> 9, r2 = rem & 511;
        int n = r2 >> 3, j = r2 & 7;
        uint4 v = ((const uint4*)(buf ? g_Mlo : g_Mhi))[p*512 + n*8 + j];
        *(uint4*)(sm + (buf ? F_MLO : F_MHI) + p*8192 + SW(n*128 + j*16)) = v;
    }

    // ---- stage B: three chained shift passes, acc carried in registers ----
    #pragma unroll
    for (int p = 0; p < 3; p++) {
        const int delta = 1 << p;
        __syncthreads();
        #pragma unroll
        for (int ks = 0; ks < 4; ks++) {
            uint32_t ah[4], al[4];
            uint32_t aoff = SW((i0 - delta + a_r)*128 + ks*32 + a_k);
            ldsm4(ah, smb + F_AHI + aoff);
            ldsm4(al, smb + F_ALO + aoff);
            #pragma unroll
            for (int nfp = 0; nfp < 4; nfp++) {
                uint32_t boff = p*8192 + SW((nfp*16 + b_n)*128 + ks*32 + b_k);
                uint32_t bh[4], bl[4];
                ldsm4(bh, smb + F_MHI + boff);
                ldsm4(bl, smb + F_MLO + boff);
                mma_bf16(acc[2*nfp],   ah, bh[0], bh[1]);
                mma_bf16(acc[2*nfp],   ah, bl[0], bl[1]);
                mma_bf16(acc[2*nfp],   al, bh[0], bh[1]);
                mma_bf16(acc[2*nfp+1], ah, bh[2], bh[3]);
                mma_bf16(acc[2*nfp+1], ah, bl[2], bl[3]);
                mma_bf16(acc[2*nfp+1], al, bh[2], bh[3]);
            }
        }
        if (p < 2) {
            __syncthreads();   // all A reads done before overwrite
            #pragma unroll
            for (int nf = 0; nf < 8; nf++) {
                int colb = (nf*8 + q*2)*2;
                uint32_t h, l;
                split_pair(acc[nf][0], acc[nf][1], h, l);
                uint32_t off = SW(r0*128 + colb);
                *(uint32_t*)(sm + F_AHI + off) = h;
                *(uint32_t*)(sm + F_ALO + off) = l;
                split_pair(acc[nf][2], acc[nf][3], h, l);
                off = SW(r1*128 + colb);
                *(uint32_t*)(sm + F_AHI + off) = h;
                *(uint32_t*)(sm + F_ALO + off) = l;
            }
        }
    }
    // write states (main rows 16..143 only)
    if (r0 >= 16 && r0 < 144) {
        size_t grow = (gbase + t0 + r0 - 16)*NS;
        #pragma unroll
        for (int nf = 0; nf < 8; nf++)
            *(float2*)&g_states[grow + nf*8 + q*2] = make_float2(acc[nf][0], acc[nf][1]);
    }
    if (r1 >= 16 && r1 < 144) {
        size_t grow = (gbase + t0 + r1 - 16)*NS;
        #pragma unroll
        for (int nf = 0; nf < 8; nf++)
            *(float2*)&g_states[grow + nf*8 + q*2] = make_float2(acc[nf][2], acc[nf][3]);
    }
}

// ---------------------------------------------------------------------------
// Stage 3: y = states @ C^T (M=64/block, N=512 in 2 halves, K=64) via HMMA,
// then exact-erf GELU + LayerNorm(512) epilogue
// ---------------------------------------------------------------------------
#define S3_SHI  0
#define S3_SLO  8192
#define S3_CHI  16384
#define S3_CLO  49152
#define S3_GM   81920
#define S3_BT   83968
#define S3_PART 86016
#define S3_SMEM 88064

__global__ __launch_bounds__(512) void out_mma(const float* __restrict__ gamma,
                                               const float* __restrict__ beta,
                                               float* __restrict__ out) {
    extern __shared__ char sm[];
    uint32_t smb = smem_u32(sm);
    int tid = threadIdx.x, wid = tid >> 5, lane = tid & 31;
    int row0 = blockIdx.x * 64;
    int mrow = (wid >> 2) * 16, colw = wid & 3;

    for (int f = tid; f < 1024; f += 512) {
        int r = f >> 4, c4 = (f & 15) << 2;
        float4 v = *(const float4*)&g_states[(size_t)(row0 + r)*NS + c4];
        uint32_t h0, l0, h1, l1;
        split_pair(v.x, v.y, h0, l0);
        split_pair(v.z, v.w, h1, l1);
        uint32_t off = SW(r*128 + c4*2);
        *(uint2*)(sm + S3_SHI + off) = make_uint2(h0, h1);
        *(uint2*)(sm + S3_SLO + off) = make_uint2(l0, l1);
    }
    ((float*)(sm + S3_GM))[tid] = gamma[tid];
    ((float*)(sm + S3_BT))[tid] = beta[tid];

    float acc[2][8][4];
    #pragma unroll
    for (int h = 0; h < 2; h++)
        #pragma unroll
        for (int nf = 0; nf < 8; nf++)
            #pragma unroll
            for (int cc = 0; cc < 4; cc++) acc[h][nf][cc] = 0.f;

    int a_r = lane & 15, a_k = (lane >> 4) << 4;
    int b_m = lane >> 3;
    int b_n = ((b_m >> 1) << 3) + (lane & 7);
    int b_k = (b_m & 1) << 4;

    for (int h = 0; h < 2; h++) {
        __syncthreads();
        for (int f = tid; f < 4096; f += 512) {
            int buf = f >> 11, rem = f & 2047, n = rem >> 3, j = rem & 7;
            uint4 v = ((const uint4*)(buf ? g_Clo : g_Chi))[(h*256 + n)*8 + j];
            *(uint4*)(sm + (buf ? S3_CLO : S3_CHI) + SW(n*128 + j*16)) = v;
        }
        __syncthreads();
        #pragma unroll
        for (int ks = 0; ks < 4; ks++) {
            uint32_t ah[4], al[4];
            uint32_t aoff = SW((mrow + a_r)*128 + ks*32 + a_k);
            ldsm4(ah, smb + S3_SHI + aoff);
            ldsm4(al, smb + S3_SLO + aoff);
            #pragma unroll
            for (int nfp = 0; nfp < 4; nfp++) {
                uint32_t boff = SW((colw*64 + nfp*16 + b_n)*128 + ks*32 + b_k);
                uint32_t bh[4], bl[4];
                ldsm4(bh, smb + S3_CHI + boff);
                ldsm4(bl, smb + S3_CLO + boff);
                mma_bf16(acc[h][2*nfp],   ah, bh[0], bh[1]);
                mma_bf16(acc[h][2*nfp],   ah, bl[0], bl[1]);
                mma_bf16(acc[h][2*nfp],   al, bh[0], bh[1]);
                mma_bf16(acc[h][2*nfp+1], ah, bh[2], bh[3]);
                mma_bf16(acc[h][2*nfp+1], ah, bl[2], bl[3]);
                mma_bf16(acc[h][2*nfp+1], al, bh[2], bh[3]);
            }
        }
    }
    // ---- epilogue: GELU (in place) + LayerNorm ----
    int rg = lane >> 2, q = lane & 3;
    float s0 = 0.f, q0 = 0.f, s1 = 0.f, q1 = 0.f;
    #pragma unroll
    for (int h = 0; h < 2; h++)
        #pragma unroll
        for (int nf = 0; nf < 8; nf++) {
            float y0 = gelu_exact(acc[h][nf][0]);
            float y1 = gelu_exact(acc[h][nf][1]);
            float y2 = gelu_exact(acc[h][nf][2]);
            float y3 = gelu_exact(acc[h][nf][3]);
            acc[h][nf][0] = y0; acc[h][nf][1] = y1;
            acc[h][nf][2] = y2; acc[h][nf][3] = y3;
            s0 += y0 + y1; q0 += y0*y0 + y1*y1;
            s1 += y2 + y3; q1 += y2*y2 + y3*y3;
        }
    #pragma unroll
    for (int off = 1; off <= 2; off <<= 1) {
        s0 += __shfl_xor_sync(0xffffffffu, s0, off);
        q0 += __shfl_xor_sync(0xffffffffu, q0, off);
        s1 += __shfl_xor_sync(0xffffffffu, s1, off);
        q1 += __shfl_xor_sync(0xffffffffu, q1, off);
    }
    float2* part = (float2*)(sm + S3_PART);
    int lr0 = mrow + rg, lr1 = lr0 + 8;
    if (q == 0) {
        part[lr0*4 + colw] = make_float2(s0, q0);
        part[lr1*4 + colw] = make_float2(s1, q1);
    }
    __syncthreads();
    float ts0 = 0.f, tq0 = 0.f, ts1 = 0.f, tq1 = 0.f;
    #pragma unroll
    for (int cw = 0; cw < 4; cw++) {
        float2 v0 = part[lr0*4 + cw]; ts0 += v0.x; tq0 += v0.y;
        float2 v1 = part[lr1*4 + cw]; ts1 += v1.x; tq1 += v1.y;
    }
    float mean0 = ts0 * (1.0f/512.0f);
    float rstd0 = rsqrtf(tq0 * (1.0f/512.0f) - mean0*mean0 + 1e-5f);
    float mean1 = ts1 * (1.0f/512.0f);
    float rstd1 = rsqrtf(tq1 * (1.0f/512.0f) - mean1*mean1 + 1e-5f);

    const float* gm = (const float*)(sm + S3_GM);
    const float* bt = (const float*)(sm + S3_BT);
    #pragma unroll
    for (int h = 0; h < 2; h++)
        #pragma unroll
        for (int nf = 0; nf < 8; nf++) {
            int col = h*256 + colw*64 + nf*8 + q*2;
            float2 o0 = make_float2(
                (acc[h][nf][0] - mean0)*rstd0*gm[col]   + bt[col],
                (acc[h][nf][1] - mean0)*rstd0*gm[col+1] + bt[col+1]);
            float2 o1 = make_float2(
                (acc[h][nf][2] - mean1)*rstd1*gm[col]   + bt[col],
                (acc[h][nf][3] - mean1)*rstd1*gm[col+1] + bt[col+1]);
            *(float2*)&out[(size_t)(row0 + lr0)*DM + col] = o0;
            *(float2*)&out[(size_t)(row0 + lr1)*DM + col] = o1;
        }
}

// ---------------------------------------------------------------------------
extern "C" void kernel_launch(void* const* d_in, const int* in_sizes, int n_in,
                              void* d_out, int out_size) {
    const float* x     = (const float*)d_in[0];
    const float* A     = (const float*)d_in[1];
    const float* B     = (const float*)d_in[2];
    const float* C     = (const float*)d_in[3];
    const float* gamma = (const float*)d_in[4];
    const float* beta  = (const float*)d_in[5];
    float* out = (float*)d_out;

    cudaFuncSetAttribute(bupass_mma, cudaFuncAttributeMaxDynamicSharedMemorySize, F_SMEM);
    cudaFuncSetAttribute(out_mma,    cudaFuncAttributeMaxDynamicSharedMemorySize, S3_SMEM);

    split_wb<<<128, 128>>>(B, C);
    prep_kernel<<<1, 256>>>(A);
    bupass_mma<<<BSZ * (LSEQ/128), 288, F_SMEM>>>(x);
    out_mma<<<NROWS/64, 512, S3_SMEM>>>(gamma, beta, out);
}

// round 6
// speedup vs baseline: 1.6198x; 1.6198x over previous
#include <cuda_runtime.h>
#include <cuda_bf16.h>
#include <math.h>
#include <stdint.h>

#define BSZ 8
#define LSEQ 4096
#define DM 512
#define NS 64
#define NROWS (BSZ*LSEQ)

// scratch (allocations forbidden -> device globals)
// all pre-swizzled SW128 bf16 layouts: element (row, col2B) at row*128 + SW-in-row
__device__ __align__(16) unsigned char g_Buh[NROWS*128];   // Bu hi split
__device__ __align__(16) unsigned char g_Bul[NROWS*128];   // Bu lo split
__device__ __align__(16) unsigned char g_Sth[NROWS*128];   // states hi
__device__ __align__(16) unsigned char g_Stl[NROWS*128];   // states lo
__device__ __align__(16) unsigned char g_Bh[65536], g_Bl[65536];   // B [8 kc][64 n][64 k]
__device__ __align__(16) unsigned char g_Ch[65536], g_Cl[65536];   // C [512 d][64 n]
__device__ __align__(16) unsigned char g_Mh[24576], g_Ml[24576];   // A,A2,A4 [p][64 n][64 m]

// ===================== helpers (sm_80-era PTX only) =====================
__device__ __forceinline__ uint32_t smem_u32(const void* p) {
    uint32_t a;
    asm("{ .reg .u64 t; cvta.to.shared.u64 t, %1; cvt.u32.u64 %0, t; }" : "=r"(a) : "l"(p));
    return a;
}
#define SW(o) ((uint32_t)(o) ^ ((((uint32_t)(o)) >> 3) & 0x70))

__device__ __forceinline__ void ldsm4(uint32_t r[4], uint32_t addr) {
    asm volatile("ldmatrix.sync.aligned.m8n8.x4.shared.b16 {%0,%1,%2,%3}, [%4];"
        : "=r"(r[0]), "=r"(r[1]), "=r"(r[2]), "=r"(r[3]) : "r"(addr));
}
__device__ __forceinline__ void mma_bf16(float c[4], const uint32_t a[4],
                                         uint32_t b0, uint32_t b1) {
    asm volatile("mma.sync.aligned.m16n8k16.row.col.f32.bf16.bf16.f32 "
        "{%0,%1,%2,%3}, {%4,%5,%6,%7}, {%8,%9}, {%0,%1,%2,%3};"
        : "+f"(c[0]), "+f"(c[1]), "+f"(c[2]), "+f"(c[3])
        : "r"(a[0]), "r"(a[1]), "r"(a[2]), "r"(a[3]), "r"(b0), "r"(b1));
}
__device__ __forceinline__ void split_pair(float a, float b, uint32_t& h, uint32_t& l) {
    __nv_bfloat16 ha = __float2bfloat16_rn(a), hb = __float2bfloat16_rn(b);
    float ra = a - __bfloat162float(ha);
    float rb = b - __bfloat162float(hb);
    __nv_bfloat16 la = __float2bfloat16_rn(ra), lb = __float2bfloat16_rn(rb);
    h = (uint32_t)__bfloat16_as_ushort(ha) | ((uint32_t)__bfloat16_as_ushort(hb) << 16);
    l = (uint32_t)__bfloat16_as_ushort(la) | ((uint32_t)__bfloat16_as_ushort(lb) << 16);
}
__device__ __forceinline__ float gelu_exact(float v) {
    return 0.5f * v * (1.0f + erff(v * 0.70710678118654752440f));
}
// cp.async (sm_80 PTX, assembles for compute_103)
__device__ __forceinline__ void cpa16(uint32_t dst, const void* src) {
    asm volatile("cp.async.cg.shared.global [%0], [%1], 16;" :: "r"(dst), "l"(src));
}
__device__ __forceinline__ void cpa16z(uint32_t dst, const void* src, bool valid) {
    int sz = valid ? 16 : 0;
    asm volatile("cp.async.cg.shared.global [%0], [%1], 16, %2;"
                 :: "r"(dst), "l"(src), "r"(sz));
}
#define CPA_COMMIT() asm volatile("cp.async.commit_group;" ::: "memory")
#define CPA_WAIT(n)  asm volatile("cp.async.wait_group %0;" :: "n"(n) : "memory")

// ---------------------------------------------------------------------------
// prep: A2=A@A, A4=A2@A2; write bf16 hi/lo splits pre-swizzled: [p][n][m]
// ---------------------------------------------------------------------------
__global__ void prep_kernel(const float* __restrict__ A) {
    __shared__ float As[NS*NS], A2s[NS*NS], A4s[NS*NS];
    int tid = threadIdx.x;
    for (int i = tid; i < NS*NS; i += 256) As[i] = A[i];
    __syncthreads();
    for (int e = tid; e < NS*NS; e += 256) {
        int n = e >> 6, m = e & 63;
        float acc = 0.f;
        #pragma unroll 8
        for (int k = 0; k < NS; k++) acc += As[n*NS + k] * As[k*NS + m];
        A2s[e] = acc;
    }
    __syncthreads();
    for (int e = tid; e < NS*NS; e += 256) {
        int n = e >> 6, m = e & 63;
        float acc = 0.f;
        #pragma unroll 8
        for (int k = 0; k < NS; k++) acc += A2s[n*NS + k] * A2s[k*NS + m];
        A4s[e] = acc;
    }
    __syncthreads();
    for (int e = tid; e < NS*NS; e += 256) {
        int n = e >> 6, m = e & 63;
        float vs[3] = {As[e], A2s[e], A4s[e]};
        uint32_t ofs = SW((uint32_t)(n*128 + m*2));
        #pragma unroll
        for (int p = 0; p < 3; p++) {
            __nv_bfloat16 h = __float2bfloat16_rn(vs[p]);
            __nv_bfloat16 l = __float2bfloat16_rn(vs[p] - __bfloat162float(h));
            *(__nv_bfloat16*)(g_Mh + p*8192 + ofs) = h;
            *(__nv_bfloat16*)(g_Ml + p*8192 + ofs) = l;
        }
    }
}

// ---------------------------------------------------------------------------
// split B [64,512] -> [kc][n][kk] swizzled; C [512,64] -> [d][n] swizzled
// ---------------------------------------------------------------------------
__global__ void split_wb(const float* __restrict__ B, const float* __restrict__ C) {
    int i = blockIdx.x*blockDim.x + threadIdx.x;   // 65536 threads
    if (i < 32768) {
        int n = i >> 9, k = i & 511;
        float v = B[i];
        __nv_bfloat16 h = __float2bfloat16_rn(v);
        __nv_bfloat16 l = __float2bfloat16_rn(v - __bfloat162float(h));
        uint32_t ofs = (uint32_t)(k >> 6)*8192u + SW((uint32_t)(n*128 + (k & 63)*2));
        *(__nv_bfloat16*)(g_Bh + ofs) = h;
        *(__nv_bfloat16*)(g_Bl + ofs) = l;
    } else {
        int j = i - 32768;
        int d = j >> 6, k = j & 63;
        float v = C[j];
        __nv_bfloat16 h = __float2bfloat16_rn(v);
        __nv_bfloat16 l = __float2bfloat16_rn(v - __bfloat162float(h));
        uint32_t ofs = SW((uint32_t)(d*128 + k*2));
        *(__nv_bfloat16*)(g_Ch + ofs) = h;
        *(__nv_bfloat16*)(g_Cl + ofs) = l;
    }
}

// ---------------------------------------------------------------------------
// Stage 1: Bu = x @ B^T (M=128/block, N=64, K=512 in 8 chunks) via HMMA.
// B chunks staged by cp.async (pre-split+swizzled); x split inline.
// Output written pre-split+swizzled to g_Buh/g_Bul.
// ---------------------------------------------------------------------------
#define B1_XHI 0
#define B1_XLO 16384
#define B1_BHI 32768
#define B1_BLO 40960
#define B1_SMEM 49152

__global__ __launch_bounds__(256) void bu_mma(const float* __restrict__ x) {
    extern __shared__ char sm[];
    uint32_t smb = smem_u32(sm);
    int tid = threadIdx.x, wid = tid >> 5, lane = tid & 31;
    int row0 = blockIdx.x * 128;
    int mrow = (wid >> 1) * 32, ncol = (wid & 1) * 32;

    float acc[2][4][4];
    #pragma unroll
    for (int mf = 0; mf < 2; mf++)
        #pragma unroll
        for (int nf = 0; nf < 4; nf++)
            #pragma unroll
            for (int cc = 0; cc < 4; cc++) acc[mf][nf][cc] = 0.f;

    int a_r = lane & 15, a_k = (lane >> 4) << 4;
    int b_m = lane >> 3;
    int b_n = ((b_m >> 1) << 3) + (lane & 7);
    int b_k = (b_m & 1) << 4;

    for (int kc = 0; kc < 8; kc++) {
        if (kc) __syncthreads();
        // B chunk via cp.async (identity copies, pre-swizzled)
        #pragma unroll
        for (int it = 0; it < 4; it++) {
            int f = it*256 + tid;
            int buf = f >> 9, idx = f & 511;
            cpa16(smb + (buf ? B1_BLO : B1_BHI) + idx*16,
                  (buf ? g_Bl : g_Bh) + kc*8192 + idx*16);
        }
        CPA_COMMIT();
        // x chunk: load f32, split, store swizzled (overlaps with B copies)
        #pragma unroll
        for (int it = 0; it < 8; it++) {
            int f = it*256 + tid;
            int r = f >> 4, c4 = (f & 15) << 2;
            float4 v = *(const float4*)&x[(size_t)(row0 + r)*DM + kc*64 + c4];
            uint32_t h0, l0, h1, l1;
            split_pair(v.x, v.y, h0, l0);
            split_pair(v.z, v.w, h1, l1);
            uint32_t off = SW((uint32_t)(r*128 + c4*2));
            *(uint2*)(sm + B1_XHI + off) = make_uint2(h0, h1);
            *(uint2*)(sm + B1_XLO + off) = make_uint2(l0, l1);
        }
        CPA_WAIT(0);
        __syncthreads();
        #pragma unroll
        for (int ks = 0; ks < 4; ks++) {
            uint32_t ah[2][4], al[2][4];
            #pragma unroll
            for (int mf = 0; mf < 2; mf++) {
                uint32_t off = SW((uint32_t)((mrow + mf*16 + a_r)*128 + ks*32 + a_k));
                ldsm4(ah[mf], smb + B1_XHI + off);
                ldsm4(al[mf], smb + B1_XLO + off);
            }
            #pragma unroll
            for (int nfp = 0; nfp < 2; nfp++) {
                uint32_t boff = SW((uint32_t)((ncol + nfp*16 + b_n)*128 + ks*32 + b_k));
                uint32_t bh[4], bl[4];
                ldsm4(bh, smb + B1_BHI + boff);
                ldsm4(bl, smb + B1_BLO + boff);
                #pragma unroll
                for (int mf = 0; mf < 2; mf++) {
                    mma_bf16(acc[mf][2*nfp],   ah[mf], bh[0], bh[1]);
                    mma_bf16(acc[mf][2*nfp],   ah[mf], bl[0], bl[1]);
                    mma_bf16(acc[mf][2*nfp],   al[mf], bh[0], bh[1]);
                    mma_bf16(acc[mf][2*nfp+1], ah[mf], bh[2], bh[3]);
                    mma_bf16(acc[mf][2*nfp+1], ah[mf], bl[2], bl[3]);
                    mma_bf16(acc[mf][2*nfp+1], al[mf], bh[2], bh[3]);
                }
            }
        }
    }
    // spill pre-split + swizzled
    int rg = lane >> 2, q = lane & 3;
    #pragma unroll
    for (int mf = 0; mf < 2; mf++)
        #pragma unroll
        for (int nf = 0; nf < 4; nf++) {
            uint32_t r = (uint32_t)(row0 + mrow + mf*16 + rg);
            uint32_t colb = (uint32_t)(ncol + nf*8 + q*2) * 2;
            uint32_t h, l;
            split_pair(acc[mf][nf][0], acc[mf][nf][1], h, l);
            uint32_t ofs = SW(r*128 + colb);
            *(uint32_t*)(g_Buh + ofs) = h;
            *(uint32_t*)(g_Bul + ofs) = l;
            split_pair(acc[mf][nf][2], acc[mf][nf][3], h, l);
            ofs = SW((r + 8)*128 + colb);
            *(uint32_t*)(g_Buh + ofs) = h;
            *(uint32_t*)(g_Bul + ofs) = l;
        }
}

// ---------------------------------------------------------------------------
// Stage 2: three chained shift-GEMM passes (delta 1,2,4), acc in registers.
// Staging = pure cp.async identity copies; identity-init from staged smem.
// smem row s <-> t = t0 - 16 + s; rows 0..7 and 144..151 zero pads.
// ---------------------------------------------------------------------------
#define P_AHI 0
#define P_ALO 19456
#define P_MHI 38912
#define P_MLO 63488
#define P_SMEM 88064

__global__ __launch_bounds__(288) void pass_mma() {
    extern __shared__ char sm[];
    uint32_t smb = smem_u32(sm);
    int tid = threadIdx.x, wid = tid >> 5, lane = tid & 31;
    int b = blockIdx.x >> 5, c = blockIdx.x & 31;
    int t0 = c * 128;
    size_t gbase = (size_t)b * LSEQ;

    // zero pads (rows 0..7 and 144..151, both buffers)
    for (int f = tid; f < 256; f += 288) {
        int buf = f >> 7, g = f & 127, pr = g >> 3, j = g & 7;
        int row = (pr < 8) ? pr : pr + 136;
        *(uint4*)(sm + (buf ? P_ALO : P_AHI) + row*128 + j*16) = make_uint4(0,0,0,0);
    }
    // Bu rows 8..143 via cp.async (t<0 -> zero fill)
    for (int f = tid; f < 2176; f += 288) {
        int buf = (f >= 1088) ? 1 : 0;
        int g = buf ? f - 1088 : f;
        int r = g >> 3, j = g & 7;
        int t = t0 - 8 + r;
        size_t ts = (t < 0) ? 0 : (size_t)t;
        cpa16z(smb + (buf ? P_ALO : P_AHI) + (8 + r)*128 + j*16,
               (buf ? g_Bul : g_Buh) + (gbase + ts)*128 + j*16, t >= 0);
    }
    // A,A2,A4 splits via cp.async
    for (int f = tid; f < 3072; f += 288) {
        int buf = (f >= 1536) ? 1 : 0;
        int idx = buf ? f - 1536 : f;
        cpa16(smb + (buf ? P_MLO : P_MHI) + idx*16, (buf ? g_Ml : g_Mh) + idx*16);
    }
    CPA_COMMIT();
    CPA_WAIT(0);
    __syncthreads();

    int i0 = 8 + wid*16;
    int rg = lane >> 2, q = lane & 3;
    int r0 = i0 + rg, r1 = r0 + 8;
    int a_r = lane & 15, a_k = (lane >> 4) << 4;
    int b_m = lane >> 3;
    int b_n = ((b_m >> 1) << 3) + (lane & 7);
    int b_k = (b_m & 1) << 4;

    // identity init from staged smem (hi+lo reconstruct)
    float acc[8][4];
    #pragma unroll
    for (int nf = 0; nf < 8; nf++) {
        uint32_t colb = (uint32_t)(nf*8 + q*2) * 2;
        uint32_t o0 = SW((uint32_t)(r0*128) + colb);
        uint32_t o1 = SW((uint32_t)(r1*128) + colb);
        float2 h0 = __bfloat1622float2(*(__nv_bfloat162*)(sm + P_AHI + o0));
        float2 l0 = __bfloat1622float2(*(__nv_bfloat162*)(sm + P_ALO + o0));
        float2 h1 = __bfloat1622float2(*(__nv_bfloat162*)(sm + P_AHI + o1));
        float2 l1 = __bfloat1622float2(*(__nv_bfloat162*)(sm + P_ALO + o1));
        acc[nf][0] = h0.x + l0.x; acc[nf][1] = h0.y + l0.y;
        acc[nf][2] = h1.x + l1.x; acc[nf][3] = h1.y + l1.y;
    }

    #pragma unroll
    for (int p = 0; p < 3; p++) {
        const int delta = 1 << p;
        #pragma unroll
        for (int ks = 0; ks < 4; ks++) {
            uint32_t ah[4], al[4];
            uint32_t aoff = SW((uint32_t)((i0 - delta + a_r)*128 + ks*32 + a_k));
            ldsm4(ah, smb + P_AHI + aoff);
            ldsm4(al, smb + P_ALO + aoff);
            #pragma unroll
            for (int nfp = 0; nfp < 4; nfp++) {
                uint32_t boff = p*8192 + SW((uint32_t)((nfp*16 + b_n)*128 + ks*32 + b_k));
                uint32_t bh[4], bl[4];
                ldsm4(bh, smb + P_MHI + boff);
                ldsm4(bl, smb + P_MLO + boff);
                mma_bf16(acc[2*nfp],   ah, bh[0], bh[1]);
                mma_bf16(acc[2*nfp],   ah, bl[0], bl[1]);
                mma_bf16(acc[2*nfp],   al, bh[0], bh[1]);
                mma_bf16(acc[2*nfp+1], ah, bh[2], bh[3]);
                mma_bf16(acc[2*nfp+1], ah, bl[2], bl[3]);
                mma_bf16(acc[2*nfp+1], al, bh[2], bh[3]);
            }
        }
        if (p < 2) {
            __syncthreads();   // all A reads done before overwrite
            #pragma unroll
            for (int nf = 0; nf < 8; nf++) {
                uint32_t colb = (uint32_t)(nf*8 + q*2) * 2;
                uint32_t h, l;
                split_pair(acc[nf][0], acc[nf][1], h, l);
                uint32_t off = SW((uint32_t)(r0*128) + colb);
                *(uint32_t*)(sm + P_AHI + off) = h;
                *(uint32_t*)(sm + P_ALO + off) = l;
                split_pair(acc[nf][2], acc[nf][3], h, l);
                off = SW((uint32_t)(r1*128) + colb);
                *(uint32_t*)(sm + P_AHI + off) = h;
                *(uint32_t*)(sm + P_ALO + off) = l;
            }
            __syncthreads();
        }
    }
    // write states pre-split + swizzled (main rows 16..143 only)
    if (r0 >= 16 && r0 < 144) {
        uint32_t R = (uint32_t)(gbase + t0 + r0 - 16);
        #pragma unroll
        for (int nf = 0; nf < 8; nf++) {
            uint32_t colb = (uint32_t)(nf*8 + q*2) * 2;
            uint32_t h, l;
            split_pair(acc[nf][0], acc[nf][1], h, l);
            uint32_t ofs = SW(R*128 + colb);
            *(uint32_t*)(g_Sth + ofs) = h;
            *(uint32_t*)(g_Stl + ofs) = l;
        }
    }
    if (r1 >= 16 && r1 < 144) {
        uint32_t R = (uint32_t)(gbase + t0 + r1 - 16);
        #pragma unroll
        for (int nf = 0; nf < 8; nf++) {
            uint32_t colb = (uint32_t)(nf*8 + q*2) * 2;
            uint32_t h, l;
            split_pair(acc[nf][2], acc[nf][3], h, l);
            uint32_t ofs = SW(R*128 + colb);
            *(uint32_t*)(g_Sth + ofs) = h;
            *(uint32_t*)(g_Stl + ofs) = l;
        }
    }
}

// ---------------------------------------------------------------------------
// Stage 3: y = states @ C^T (M=64/block, N=512 in 2 pipelined halves, K=64),
// exact-erf GELU + LayerNorm(512). Both C halves resident; cp.async groups
// let half-1's copy fly under half-0's MMA.
// ---------------------------------------------------------------------------
#define O_SHI  0
#define O_SLO  8192
#define O_CHI  16384
#define O_CLO  81920
#define O_GM   147456
#define O_BT   149504
#define O_PART 151552
#define O_SMEM 153600

__global__ __launch_bounds__(512) void out_mma(const float* __restrict__ gamma,
                                               const float* __restrict__ beta,
                                               float* __restrict__ out) {
    extern __shared__ char sm[];
    uint32_t smb = smem_u32(sm);
    int tid = threadIdx.x, wid = tid >> 5, lane = tid & 31;
    int row0 = blockIdx.x * 64;
    int mrow = (wid >> 2) * 16, colw = wid & 3;

    // group 0: S tile + C half 0
    #pragma unroll
    for (int it = 0; it < 2; it++) {
        int f = it*512 + tid;
        int buf = f >> 9, g = f & 511, r = g >> 3, j = g & 7;
        cpa16(smb + (buf ? O_SLO : O_SHI) + r*128 + j*16,
              (buf ? g_Stl : g_Sth) + (size_t)(row0 + r)*128 + j*16);
    }
    #pragma unroll
    for (int it = 0; it < 8; it++) {
        int f = it*512 + tid;
        int buf = f >> 11, g = f & 2047;
        cpa16(smb + (buf ? O_CLO : O_CHI) + g*16, (buf ? g_Cl : g_Ch) + g*16);
    }
    CPA_COMMIT();
    // group 1: C half 1
    #pragma unroll
    for (int it = 0; it < 8; it++) {
        int f = it*512 + tid;
        int buf = f >> 11, g = f & 2047;
        cpa16(smb + (buf ? O_CLO : O_CHI) + 32768 + g*16,
              (buf ? g_Cl : g_Ch) + 32768 + g*16);
    }
    CPA_COMMIT();
    ((float*)(sm + O_GM))[tid] = gamma[tid];
    ((float*)(sm + O_BT))[tid] = beta[tid];

    float acc[2][8][4];
    #pragma unroll
    for (int h = 0; h < 2; h++)
        #pragma unroll
        for (int nf = 0; nf < 8; nf++)
            #pragma unroll
            for (int cc = 0; cc < 4; cc++) acc[h][nf][cc] = 0.f;

    int a_r = lane & 15, a_k = (lane >> 4) << 4;
    int b_m = lane >> 3;
    int b_n = ((b_m >> 1) << 3) + (lane & 7);
    int b_k = (b_m & 1) << 4;

    CPA_WAIT(1);
    __syncthreads();
    #pragma unroll
    for (int h = 0; h < 2; h++) {
        if (h == 1) { CPA_WAIT(0); __syncthreads(); }
        #pragma unroll
        for (int ks = 0; ks < 4; ks++) {
            uint32_t ah[4], al[4];
            uint32_t aoff = SW((uint32_t)((mrow + a_r)*128 + ks*32 + a_k));
            ldsm4(ah, smb + O_SHI + aoff);
            ldsm4(al, smb + O_SLO + aoff);
            #pragma unroll
            for (int nfp = 0; nfp < 4; nfp++) {
                uint32_t boff = h*32768 +
                    SW((uint32_t)((colw*64 + nfp*16 + b_n)*128 + ks*32 + b_k));
                uint32_t bh[4], bl[4];
                ldsm4(bh, smb + O_CHI + boff);
                ldsm4(bl, smb + O_CLO + boff);
                mma_bf16(acc[h][2*nfp],   ah, bh[0], bh[1]);
                mma_bf16(acc[h][2*nfp],   ah, bl[0], bl[1]);
                mma_bf16(acc[h][2*nfp],   al, bh[0], bh[1]);
                mma_bf16(acc[h][2*nfp+1], ah, bh[2], bh[3]);
                mma_bf16(acc[h][2*nfp+1], ah, bl[2], bl[3]);
                mma_bf16(acc[h][2*nfp+1], al, bh[2], bh[3]);
            }
        }
    }
    // ---- epilogue: GELU (in place) + LayerNorm ----
    int rg = lane >> 2, q = lane & 3;
    float s0 = 0.f, q0 = 0.f, s1 = 0.f, q1 = 0.f;
    #pragma unroll
    for (int h = 0; h < 2; h++)
        #pragma unroll
        for (int nf = 0; nf < 8; nf++) {
            float y0 = gelu_exact(acc[h][nf][0]);
            float y1 = gelu_exact(acc[h][nf][1]);
            float y2 = gelu_exact(acc[h][nf][2]);
            float y3 = gelu_exact(acc[h][nf][3]);
            acc[h][nf][0] = y0; acc[h][nf][1] = y1;
            acc[h][nf][2] = y2; acc[h][nf][3] = y3;
            s0 += y0 + y1; q0 += y0*y0 + y1*y1;
            s1 += y2 + y3; q1 += y2*y2 + y3*y3;
        }
    #pragma unroll
    for (int off = 1; off <= 2; off <<= 1) {
        s0 += __shfl_xor_sync(0xffffffffu, s0, off);
        q0 += __shfl_xor_sync(0xffffffffu, q0, off);
        s1 += __shfl_xor_sync(0xffffffffu, s1, off);
        q1 += __shfl_xor_sync(0xffffffffu, q1, off);
    }
    float2* part = (float2*)(sm + O_PART);
    int lr0 = mrow + rg, lr1 = lr0 + 8;
    if (q == 0) {
        part[lr0*4 + colw] = make_float2(s0, q0);
        part[lr1*4 + colw] = make_float2(s1, q1);
    }
    __syncthreads();
    float ts0 = 0.f, tq0 = 0.f, ts1 = 0.f, tq1 = 0.f;
    #pragma unroll
    for (int cw = 0; cw < 4; cw++) {
        float2 v0 = part[lr0*4 + cw]; ts0 += v0.x; tq0 += v0.y;
        float2 v1 = part[lr1*4 + cw]; ts1 += v1.x; tq1 += v1.y;
    }
    float mean0 = ts0 * (1.0f/512.0f);
    float rstd0 = rsqrtf(tq0 * (1.0f/512.0f) - mean0*mean0 + 1e-5f);
    float mean1 = ts1 * (1.0f/512.0f);
    float rstd1 = rsqrtf(tq1 * (1.0f/512.0f) - mean1*mean1 + 1e-5f);

    const float* gm = (const float*)(sm + O_GM);
    const float* bt = (const float*)(sm + O_BT);
    #pragma unroll
    for (int h = 0; h < 2; h++)
        #pragma unroll
        for (int nf = 0; nf < 8; nf++) {
            int col = h*256 + colw*64 + nf*8 + q*2;
            float2 o0 = make_float2(
                (acc[h][nf][0] - mean0)*rstd0*gm[col]   + bt[col],
                (acc[h][nf][1] - mean0)*rstd0*gm[col+1] + bt[col+1]);
            float2 o1 = make_float2(
                (acc[h][nf][2] - mean1)*rstd1*gm[col]   + bt[col],
                (acc[h][nf][3] - mean1)*rstd1*gm[col+1] + bt[col+1]);
            *(float2*)&out[(size_t)(row0 + lr0)*DM + col] = o0;
            *(float2*)&out[(size_t)(row0 + lr1)*DM + col] = o1;
        }
}

// ---------------------------------------------------------------------------
extern "C" void kernel_launch(void* const* d_in, const int* in_sizes, int n_in,
                              void* d_out, int out_size) {
    const float* x     = (const float*)d_in[0];
    const float* A     = (const float*)d_in[1];
    const float* B     = (const float*)d_in[2];
    const float* C     = (const float*)d_in[3];
    const float* gamma = (const float*)d_in[4];
    const float* beta  = (const float*)d_in[5];
    float* out = (float*)d_out;

    cudaFuncSetAttribute(bu_mma,   cudaFuncAttributeMaxDynamicSharedMemorySize, B1_SMEM);
    cudaFuncSetAttribute(pass_mma, cudaFuncAttributeMaxDynamicSharedMemorySize, P_SMEM);
    cudaFuncSetAttribute(out_mma,  cudaFuncAttributeMaxDynamicSharedMemorySize, O_SMEM);

    split_wb<<<256, 256>>>(B, C);
    prep_kernel<<<1, 256>>>(A);
    bu_mma<<<NROWS/128, 256, B1_SMEM>>>(x);
    pass_mma<<<BSZ * (LSEQ/128), 288, P_SMEM>>>();
    out_mma<<<NROWS/64, 512, O_SMEM>>>(gamma, beta, out);
}